// round 9
// baseline (speedup 1.0000x reference)
#include <cuda_runtime.h>
#include <math.h>
#include <stddef.h>
#include <stdint.h>

// Problem dims
#define B_  64
#define T_  2048
#define I_  128
#define H_  256
#define G4  1024      // 4*H
#define C_  64

// recurrence: 16 clusters x 8 CTAs; cluster owns 4 batches; CTA owns 32-u tile
#define NGRP 16
#define GBLK 8
#define CB   4

typedef unsigned long long ull;

// ---------------- scratch (static device allocations; no cudaMalloc) --------
__device__ float g_xg   [(size_t)B_ * T_ * G4];   // 512 MB gate preacts
__device__ float g_hseq [(size_t)B_ * T_ * H_];   // 128 MB layer-0 h sequence / y0
__device__ float g_hfinal[B_ * H_];               // layer-1 final h

// ---------------- helpers ---------------------------------------------------
__device__ __forceinline__ ull ffma2(ull a, ull b, ull c) {
    ull d;
    asm("fma.rn.f32x2 %0, %1, %2, %3;" : "=l"(d) : "l"(a), "l"(b), "l"(c));
    return d;
}
__device__ __forceinline__ ull fadd2(ull a, ull b) {
    ull d;
    asm("add.rn.f32x2 %0, %1, %2;" : "=l"(d) : "l"(a), "l"(b));
    return d;
}
__device__ __forceinline__ float hsum2(ull v) {
    union { ull u; float2 f; } cv; cv.u = v;
    return cv.f.x + cv.f.y;
}
__device__ __forceinline__ void split4(const float4& v, ull& lo, ull& hi) {
    union { float4 f; ull u[2]; } cv; cv.f = v;
    lo = cv.u[0]; hi = cv.u[1];
}
__device__ __forceinline__ ull dup2(float f) {
    ull d; unsigned u = __float_as_uint(f);
    asm("mov.b64 %0, {%1, %1};" : "=l"(d) : "r"(u));
    return d;
}
__device__ __forceinline__ uint32_t smem_u32(const void* p) {
    uint32_t a;
    asm("{ .reg .u64 t; cvta.to.shared.u64 t, %1; cvt.u32.u64 %0, t; }" : "=r"(a) : "l"(p));
    return a;
}
__device__ __forceinline__ float fsigm(float x) { return 1.0f / (1.0f + __expf(-x)); }
__device__ __forceinline__ float ftanh(float x) { return 2.0f / (1.0f + __expf(-2.0f * x)) - 1.0f; }

// mbarrier wait with cluster-scope acquire (DSMEM producer-consumer)
__device__ __forceinline__ void mbar_wait_cluster(uint32_t addr, uint32_t parity) {
    asm volatile(
        "{\n\t"
        ".reg .pred P;\n\t"
        "WAIT_%=:\n\t"
        "mbarrier.try_wait.parity.acquire.cluster.shared::cta.b64 P, [%0], %1, 0x989680;\n\t"
        "@P bra.uni DONE_%=;\n\t"
        "bra.uni WAIT_%=;\n\t"
        "DONE_%=:\n\t"
        "}"
        :: "r"(addr), "r"(parity) : "memory");
}

// ---------------- phase A: xg = A @ W^T + (bih + bhh) -----------------------
// BM=128, BN=128, BK=16, 256 threads, 8m x 8n tile, n-packed FFMA2 accums.
// As [k][m] scalar (read broadcast + register dup); Ws [k][n] transposed.
#define AS_PITCH 132
#define WS_PITCH 132

template<int K, int USE_HSEQ>
__global__ void __launch_bounds__(256, 2) sgemm_xg(const float* __restrict__ Ain,
                                                   const float* __restrict__ W,
                                                   const float* __restrict__ bih,
                                                   const float* __restrict__ bhh)
{
    const float* A = USE_HSEQ ? (const float*)g_hseq : Ain;
    const int n0 = blockIdx.x * 128;
    const int m0 = blockIdx.y * 128;

    __shared__ __align__(16) float As[16 * AS_PITCH];
    __shared__ __align__(16) float Ws[16 * WS_PITCH];

    const int tid  = threadIdx.x;
    const int tx   = tid & 15;       // n = n0 + 4*tx (+64)
    const int ty   = tid >> 4;       // m = m0 + 8*ty + i
    const int lrow = tid >> 2;       // load row 0..63
    const int lkq  = (tid & 3) * 4;  // k quad

    const float* Ag = A + (size_t)(m0 + lrow) * K + lkq;
    const float* Wg = W + (size_t)(n0 + lrow) * K + lkq;

    ull acc[8][4];
#pragma unroll
    for (int i = 0; i < 8; ++i)
#pragma unroll
        for (int j = 0; j < 4; ++j) acc[i][j] = 0ull;

    auto stage = [&](const float4& a0, const float4& a1,
                     const float4& w0, const float4& w1) {
        const float av0[4] = {a0.x, a0.y, a0.z, a0.w};
        const float av1[4] = {a1.x, a1.y, a1.z, a1.w};
        const float wv0[4] = {w0.x, w0.y, w0.z, w0.w};
        const float wv1[4] = {w1.x, w1.y, w1.z, w1.w};
#pragma unroll
        for (int d = 0; d < 4; ++d) {
            int kr = lkq + d;
            As[kr * AS_PITCH + lrow]      = av0[d];
            As[kr * AS_PITCH + lrow + 64] = av1[d];
            Ws[kr * WS_PITCH + lrow]      = wv0[d];
            Ws[kr * WS_PITCH + lrow + 64] = wv1[d];
        }
    };

    {
        float4 a0 = __ldg((const float4*)Ag);
        float4 a1 = __ldg((const float4*)(Ag + (size_t)64 * K));
        float4 w0 = __ldg((const float4*)Wg);
        float4 w1 = __ldg((const float4*)(Wg + (size_t)64 * K));
        stage(a0, a1, w0, w1);
    }
    __syncthreads();

    const int NT = K / 16;
    for (int t = 0; t < NT; ++t) {
        float4 na0, na1, nw0, nw1;
        if (t + 1 < NT) {
            const float* Ag2 = Ag + (t + 1) * 16;
            const float* Wg2 = Wg + (t + 1) * 16;
            na0 = __ldg((const float4*)Ag2);
            na1 = __ldg((const float4*)(Ag2 + (size_t)64 * K));
            nw0 = __ldg((const float4*)Wg2);
            nw1 = __ldg((const float4*)(Wg2 + (size_t)64 * K));
        }

#pragma unroll
        for (int kk = 0; kk < 16; ++kk) {
            ull ad[8];
            {
                float4 v0 = *(const float4*)&As[kk * AS_PITCH + 8 * ty];
                float4 v1 = *(const float4*)&As[kk * AS_PITCH + 8 * ty + 4];
                ad[0] = dup2(v0.x); ad[1] = dup2(v0.y); ad[2] = dup2(v0.z); ad[3] = dup2(v0.w);
                ad[4] = dup2(v1.x); ad[5] = dup2(v1.y); ad[6] = dup2(v1.z); ad[7] = dup2(v1.w);
            }
            ull wp_[4];
            {
                float4 v0 = *(const float4*)&Ws[kk * WS_PITCH + 4 * tx];
                float4 v1 = *(const float4*)&Ws[kk * WS_PITCH + 64 + 4 * tx];
                split4(v0, wp_[0], wp_[1]);
                split4(v1, wp_[2], wp_[3]);
            }
#pragma unroll
            for (int i = 0; i < 8; ++i)
#pragma unroll
                for (int j = 0; j < 4; ++j)
                    acc[i][j] = ffma2(ad[i], wp_[j], acc[i][j]);
        }
        __syncthreads();
        if (t + 1 < NT) {
            stage(na0, na1, nw0, nw1);
            __syncthreads();
        }
    }

    const int nA = n0 + 4 * tx;
    const int nB = n0 + 64 + 4 * tx;
    ull bA0, bA1, bB0, bB1;
    {
        float4 biA = __ldg((const float4*)&bih[nA]);
        float4 bhA = __ldg((const float4*)&bhh[nA]);
        float4 biB = __ldg((const float4*)&bih[nB]);
        float4 bhB = __ldg((const float4*)&bhh[nB]);
        float4 sA = make_float4(biA.x + bhA.x, biA.y + bhA.y, biA.z + bhA.z, biA.w + bhA.w);
        float4 sB = make_float4(biB.x + bhB.x, biB.y + bhB.y, biB.z + bhB.z, biB.w + bhB.w);
        split4(sA, bA0, bA1);
        split4(sB, bB0, bB1);
    }
#pragma unroll
    for (int i = 0; i < 8; ++i) {
        size_t m = (size_t)m0 + 8 * ty + i;
        union { ull u[2]; float4 f; } oA, oB;
        oA.u[0] = fadd2(acc[i][0], bA0);
        oA.u[1] = fadd2(acc[i][1], bA1);
        oB.u[0] = fadd2(acc[i][2], bB0);
        oB.u[1] = fadd2(acc[i][3], bB1);
        *(float4*)&g_xg[m * G4 + nA] = oA.f;
        *(float4*)&g_xg[m * G4 + nB] = oB.f;
    }
}

// ---------------- phase B: cluster recurrent scan (DSMEM + mbarrier) --------
// 128 CTAs = 16 clusters of 8, 256 thr. Cluster = 4 batches; CTA = 32-u tile.
// h double-buffered in SMEM; gate threads push h(t+1) to all 8 CTAs via
// st.shared::cluster; leader posts mbarrier.arrive on all 8 barriers after a
// 128-thread named bar (cumulative release); all threads try_wait.acquire.
// part double-buffered -> only one __syncthreads per step.
template<int FINAL_ONLY>
__global__ void __cluster_dims__(GBLK, 1, 1) __launch_bounds__(256, 1)
recur_kernel(const float* __restrict__ Whh, const float* __restrict__ mask)
{
    __shared__ __align__(16) float h_sh[2][CB][H_];      // 8 KB
    __shared__ __align__(16) float part[2][8][CB][128];  // 32 KB
    __shared__ __align__(8) unsigned long long mbar_s;

    const int tid = threadIdx.x;
    uint32_t rank;
    asm("mov.u32 %0, %%cluster_ctarank;" : "=r"(rank));
    const int grp = blockIdx.x / GBLK;   // 0..15
    const int B0  = grp * CB;
    const int u0  = (int)rank * 32;
    const int ksub = tid >> 5;           // 0..7
    const int tsub = tid & 31;           // u within tile

    // weights: 4 gate rows x 32 k (16 ull each), resident all 2048 steps
    ull w2[4][16];
#pragma unroll
    for (int g = 0; g < 4; ++g) {
        const ulonglong2* wp =
            (const ulonglong2*)(Whh + (size_t)(g * 256 + u0 + tsub) * H_ + ksub * 32);
#pragma unroll
        for (int i = 0; i < 8; ++i) {
            ulonglong2 v = __ldg(wp + i);
            w2[g][2 * i]     = v.x;
            w2[g][2 * i + 1] = v.y;
        }
    }

    // h(0) = 0 in both buffers
    for (int i = tid; i < 2 * CB * H_; i += 256) ((float*)h_sh)[i] = 0.0f;

    const uint32_t mbar   = smem_u32(&mbar_s);
    const uint32_t h_base = smem_u32(&h_sh[0][0][0]);
    if (tid == 0) {
        asm volatile("mbarrier.init.shared.b64 [%0], %1;" :: "r"(mbar), "r"(GBLK) : "memory");
    }

    // stage-2 identity (threads < 128: one (b,u) cell)
    const int b2 = (tid >> 5) & 3;
    const int u2 = tid & 31;
    float c_state = 0.0f;
    const float* xgbase = g_xg + (size_t)(B0 + b2) * T_ * G4 + u0 + u2;
    const float* maskp  = mask + (size_t)(B0 + b2) * T_;
    float x0, x1, x2, x3, mval;
    if (tid < 128) {
        x0 = __ldg(xgbase);
        x1 = __ldg(xgbase + 256);
        x2 = __ldg(xgbase + 512);
        x3 = __ldg(xgbase + 768);
        mval = __ldg(maskp);
    }

    __syncthreads();
    // one-time: all CTAs' mbarriers + h buffers initialized before any traffic
    asm volatile("barrier.cluster.arrive.aligned;" ::: "memory");
    asm volatile("barrier.cluster.wait.aligned;"   ::: "memory");

    for (int step = 0; step < T_; ++step) {
        const int p = step & 1;

        // ---- stage-1: broadcast LDS.128 h reads feed 4 gate rows ----
        ull acc[4][CB];
#pragma unroll
        for (int g = 0; g < 4; ++g)
#pragma unroll
            for (int b = 0; b < CB; ++b) acc[g][b] = 0ull;
#pragma unroll
        for (int b = 0; b < CB; ++b) {
            const ulonglong2* hp = (const ulonglong2*)&h_sh[p][b][ksub * 32];
#pragma unroll
            for (int kk = 0; kk < 8; ++kk) {
                ulonglong2 hv = hp[kk];
#pragma unroll
                for (int g = 0; g < 4; ++g) {
                    acc[g][b] = ffma2(w2[g][2 * kk],     hv.x, acc[g][b]);
                    acc[g][b] = ffma2(w2[g][2 * kk + 1], hv.y, acc[g][b]);
                }
            }
        }
#pragma unroll
        for (int g = 0; g < 4; ++g)
#pragma unroll
            for (int b = 0; b < CB; ++b)
                part[p][ksub][b][g * 32 + tsub] = hsum2(acc[g][b]);
        __syncthreads();   // part[p] ready (also fences h_sh[p] reads vs next pushes)

        if (tid < 128) {
            // ---- stage-2: gates + state update ----
            float s0 = x0, s1 = x1, s2 = x2, s3 = x3;
#pragma unroll
            for (int ks = 0; ks < 8; ++ks) {
                s0 += part[p][ks][b2][ 0 + u2];
                s1 += part[p][ks][b2][32 + u2];
                s2 += part[p][ks][b2][64 + u2];
                s3 += part[p][ks][b2][96 + u2];
            }
            float c = fsigm(s1) * c_state + fsigm(s0) * ftanh(s2);
            float h = fsigm(s3) * ftanh(c);
            h *= mval; c *= mval;
            c_state = c;

            // push h(t+1) into every CTA's h_sh[p^1] (incl. self)
            const uint32_t loff = h_base + ((((p ^ 1) * CB + b2) * H_) + u0 + u2) * 4u;
            const uint32_t hb = __float_as_uint(h);
#pragma unroll
            for (int r = 0; r < GBLK; ++r) {
                uint32_t ra;
                asm("mapa.shared::cluster.u32 %0, %1, %2;" : "=r"(ra) : "r"(loff), "r"(r));
                asm volatile("st.shared::cluster.b32 [%0], %1;" :: "r"(ra), "r"(hb) : "memory");
            }

            // off-critical-path: hseq/final store + next-step input prefetch
            if (!FINAL_ONLY) {
                g_hseq[((size_t)(B0 + b2) * T_ + step) * H_ + u0 + u2] = h;
            } else if (step == T_ - 1) {
                g_hfinal[(B0 + b2) * H_ + u0 + u2] = h;
            }
            int sn = (step + 1 < T_) ? step + 1 : step;
            const float* xp = xgbase + (size_t)sn * G4;
            x0 = __ldg(xp);
            x1 = __ldg(xp + 256);
            x2 = __ldg(xp + 512);
            x3 = __ldg(xp + 768);
            mval = __ldg(maskp + sn);

            // order this CTA's 128 pushes, then leader releases to all 8 mbars
            asm volatile("bar.sync 1, 128;" ::: "memory");
            if (tid == 0) {
#pragma unroll
                for (int r = 0; r < GBLK; ++r) {
                    uint32_t ra;
                    asm("mapa.shared::cluster.u32 %0, %1, %2;" : "=r"(ra) : "r"(mbar), "r"(r));
                    asm volatile("mbarrier.arrive.shared::cluster.b64 _, [%0];" :: "r"(ra) : "memory");
                }
            }
        }

        // wait: all 8 CTAs delivered h(t+1) (phase parity = step&1)
        mbar_wait_cluster(mbar, (uint32_t)(step & 1));
    }

    // no CTA exits while peers might still address its SMEM
    asm volatile("barrier.cluster.arrive.aligned;" ::: "memory");
    asm volatile("barrier.cluster.wait.aligned;"   ::: "memory");
}

// ---------------- LN + ReLU over layer-0 output (in place) ------------------
__global__ void ln_relu_kernel(const float* __restrict__ g, const float* __restrict__ b)
{
    int row  = blockIdx.x * 8 + (threadIdx.x >> 5);
    int lane = threadIdx.x & 31;
    float* p = g_hseq + (size_t)row * H_;
    float4 v0 = *(float4*)(p + lane * 4);
    float4 v1 = *(float4*)(p + 128 + lane * 4);
    float s = v0.x + v0.y + v0.z + v0.w + v1.x + v1.y + v1.z + v1.w;
    float q = v0.x*v0.x + v0.y*v0.y + v0.z*v0.z + v0.w*v0.w
            + v1.x*v1.x + v1.y*v1.y + v1.z*v1.z + v1.w*v1.w;
#pragma unroll
    for (int o = 16; o; o >>= 1) {
        s += __shfl_xor_sync(0xffffffffu, s, o);
        q += __shfl_xor_sync(0xffffffffu, q, o);
    }
    float mu  = s * (1.0f / 256.0f);
    float var = q * (1.0f / 256.0f) - mu * mu;
    float rs  = rsqrtf(var + 1e-5f);
    int u = lane * 4;
    float4 G0 = *(const float4*)(g + u);       float4 Bb0 = *(const float4*)(b + u);
    float4 G1 = *(const float4*)(g + 128 + u); float4 Bb1 = *(const float4*)(b + 128 + u);
    v0.x = fmaxf(0.0f, (v0.x - mu) * rs * G0.x + Bb0.x);
    v0.y = fmaxf(0.0f, (v0.y - mu) * rs * G0.y + Bb0.y);
    v0.z = fmaxf(0.0f, (v0.z - mu) * rs * G0.z + Bb0.z);
    v0.w = fmaxf(0.0f, (v0.w - mu) * rs * G0.w + Bb0.w);
    v1.x = fmaxf(0.0f, (v1.x - mu) * rs * G1.x + Bb1.x);
    v1.y = fmaxf(0.0f, (v1.y - mu) * rs * G1.y + Bb1.y);
    v1.z = fmaxf(0.0f, (v1.z - mu) * rs * G1.z + Bb1.z);
    v1.w = fmaxf(0.0f, (v1.w - mu) * rs * G1.w + Bb1.w);
    *(float4*)(p + lane * 4)       = v0;
    *(float4*)(p + 128 + lane * 4) = v1;
}

// ---------------- final: LN + ReLU + FC on last-step h of layer 1 -----------
__global__ void final_kernel(const float* __restrict__ lng, const float* __restrict__ lnb,
                             const float* __restrict__ fcW, const float* __restrict__ fcb,
                             float* __restrict__ out)
{
    int b = blockIdx.x;
    int t = threadIdx.x;
    __shared__ float ssum[8], sq[8];
    __shared__ float y[256];
    __shared__ float stats[2];
    float v = g_hfinal[b * H_ + t];
    float s = v, q = v * v;
#pragma unroll
    for (int o = 16; o; o >>= 1) {
        s += __shfl_xor_sync(0xffffffffu, s, o);
        q += __shfl_xor_sync(0xffffffffu, q, o);
    }
    if ((t & 31) == 0) { ssum[t >> 5] = s; sq[t >> 5] = q; }
    __syncthreads();
    if (t == 0) {
        float S = 0.0f, Q = 0.0f;
        for (int i = 0; i < 8; ++i) { S += ssum[i]; Q += sq[i]; }
        float mu  = S * (1.0f / 256.0f);
        float var = Q * (1.0f / 256.0f) - mu * mu;
        stats[0] = mu;
        stats[1] = rsqrtf(var + 1e-5f);
    }
    __syncthreads();
    y[t] = fmaxf(0.0f, (v - stats[0]) * stats[1] * lng[t] + lnb[t]);
    __syncthreads();
    if (t < C_) {
        float a = fcb[t];
        const float* wr = fcW + (size_t)t * H_;
#pragma unroll 8
        for (int u = 0; u < H_; ++u) a = fmaf(y[u], wr[u], a);
        out[b * C_ + t] = a;
    }
}

// ---------------- host entry -------------------------------------------------
extern "C" void kernel_launch(void* const* d_in, const int* in_sizes, int n_in,
                              void* d_out, int out_size)
{
    const float* seq  = (const float*)d_in[0];
    const float* mask = (const float*)d_in[1];
    const float* Wih0 = (const float*)d_in[2];
    const float* Whh0 = (const float*)d_in[3];
    const float* bih0 = (const float*)d_in[4];
    const float* bhh0 = (const float*)d_in[5];
    const float* lng0 = (const float*)d_in[6];
    const float* lnb0 = (const float*)d_in[7];
    const float* Wih1 = (const float*)d_in[8];
    const float* Whh1 = (const float*)d_in[9];
    const float* bih1 = (const float*)d_in[10];
    const float* bhh1 = (const float*)d_in[11];
    const float* lng1 = (const float*)d_in[12];
    const float* lnb1 = (const float*)d_in[13];
    const float* fcW  = (const float*)d_in[14];
    const float* fcb  = (const float*)d_in[15];
    float* out = (float*)d_out;

    const int M = B_ * T_;               // 131072
    dim3 gemm_grid(G4 / 128, M / 128);   // (8, 1024)

    // ---- layer 0 ----
    sgemm_xg<I_, 0><<<gemm_grid, 256>>>(seq, Wih0, bih0, bhh0);
    recur_kernel<0><<<NGRP * GBLK, 256>>>(Whh0, mask);
    ln_relu_kernel<<<M / 8, 256>>>(lng0, lnb0);

    // ---- layer 1 ----
    sgemm_xg<H_, 1><<<gemm_grid, 256>>>(nullptr, Wih1, bih1, bhh1);
    recur_kernel<1><<<NGRP * GBLK, 256>>>(Whh1, mask);

    // ---- head ----
    final_kernel<<<B_, 256>>>(lng1, lnb1, fcW, fcb, out);
}

// round 10
// speedup vs baseline: 1.8547x; 1.8547x over previous
#include <cuda_runtime.h>
#include <math.h>
#include <stddef.h>
#include <stdint.h>

// Problem dims
#define B_  64
#define T_  2048
#define I_  128
#define H_  256
#define G4  1024      // 4*H
#define C_  64

// recurrence: 16 groups x 8 blocks; group owns 4 batches; block owns 32-u tile
#define NGRP 16
#define GBLK 8
#define CB   4

typedef unsigned long long ull;

// ---------------- scratch (static device allocations; no cudaMalloc) --------
__device__ float    g_xg   [(size_t)B_ * T_ * G4];   // 512 MB gate preacts
__device__ float    g_hseq [(size_t)B_ * T_ * H_];   // 128 MB layer-0 h sequence / y0
__device__ float    g_hx   [2][NGRP][CB * H_];       // double-buffered group h slabs
__device__ float    g_hfinal[B_ * H_];               // layer-1 final h
__device__ unsigned g_flag [NGRP][32];               // per-block step tags (128B/group)
__device__ int      g_tstart[B_];                    // per-batch tail start (last reset + 1)

// ---------------- helpers ---------------------------------------------------
__device__ __forceinline__ ull ffma2(ull a, ull b, ull c) {
    ull d;
    asm("fma.rn.f32x2 %0, %1, %2, %3;" : "=l"(d) : "l"(a), "l"(b), "l"(c));
    return d;
}
__device__ __forceinline__ ull fadd2(ull a, ull b) {
    ull d;
    asm("add.rn.f32x2 %0, %1, %2;" : "=l"(d) : "l"(a), "l"(b));
    return d;
}
__device__ __forceinline__ float hsum2(ull v) {
    union { ull u; float2 f; } cv; cv.u = v;
    return cv.f.x + cv.f.y;
}
__device__ __forceinline__ void split4(const float4& v, ull& lo, ull& hi) {
    union { float4 f; ull u[2]; } cv; cv.f = v;
    lo = cv.u[0]; hi = cv.u[1];
}
__device__ __forceinline__ ull dup2(float f) {
    ull d; unsigned u = __float_as_uint(f);
    asm("mov.b64 %0, {%1, %1};" : "=l"(d) : "r"(u));
    return d;
}
__device__ __forceinline__ float fsigm(float x) { return 1.0f / (1.0f + __expf(-x)); }
__device__ __forceinline__ float ftanh(float x) { return 2.0f / (1.0f + __expf(-2.0f * x)) - 1.0f; }

// release/acquire flag ops (gpu scope, bypass L1)
__device__ __forceinline__ void st_release_gpu(unsigned* p, unsigned v) {
    asm volatile("st.release.gpu.u32 [%0], %1;" :: "l"(p), "r"(v) : "memory");
}
__device__ __forceinline__ unsigned ld_relaxed_gpu(const unsigned* p) {
    unsigned v;
    asm volatile("ld.relaxed.gpu.u32 %0, [%1];" : "=r"(v) : "l"(p) : "memory");
    return v;
}
__device__ __forceinline__ unsigned ld_acquire_gpu(const unsigned* p) {
    unsigned v;
    asm volatile("ld.acquire.gpu.u32 %0, [%1];" : "=r"(v) : "l"(p) : "memory");
    return v;
}

// ---------------- init: zero flags -------------------------------------------
__global__ void init_bar() {
    int i = blockIdx.x * blockDim.x + threadIdx.x;
    if (i < NGRP * 32) ((unsigned*)g_flag)[i] = 0u;
}

// ---------------- tail scan: last reset position per batch -------------------
__global__ void tail_kernel(const float* __restrict__ mask) {
    int b = blockIdx.x;
    int lane = threadIdx.x;
    int best = -1;
    for (int t = lane; t < T_; t += 32) {
        if (mask[(size_t)b * T_ + t] == 0.0f && t > best) best = t;
    }
#pragma unroll
    for (int o = 16; o; o >>= 1) {
        int v = __shfl_xor_sync(0xffffffffu, best, o);
        if (v > best) best = v;
    }
    if (lane == 0) g_tstart[b] = best + 1;
}

// ---------------- phase A: xg = A @ W^T + (bih + bhh) -----------------------
// BM=128, BN=128, BK=16, 256 threads, 8m x 8n tile, n-packed FFMA2 accums.
// As [k][m] scalar (read broadcast + register dup); Ws [k][n] transposed.
// TAILSKIP: early-exit tiles entirely below the batch's tail start.
#define AS_PITCH 132
#define WS_PITCH 132

template<int K, int USE_HSEQ, int TAILSKIP>
__global__ void __launch_bounds__(256, 2) sgemm_xg(const float* __restrict__ Ain,
                                                   const float* __restrict__ W,
                                                   const float* __restrict__ bih,
                                                   const float* __restrict__ bhh)
{
    const float* A = USE_HSEQ ? (const float*)g_hseq : Ain;
    const int n0 = blockIdx.x * 128;
    const int m0 = blockIdx.y * 128;

    if (TAILSKIP) {
        int batch = m0 >> 11;               // 2048 rows per batch, tiles don't cross
        int tile_end = (m0 & 2047) + 127;
        if (tile_end < g_tstart[batch]) return;
    }

    __shared__ __align__(16) float As[16 * AS_PITCH];
    __shared__ __align__(16) float Ws[16 * WS_PITCH];

    const int tid  = threadIdx.x;
    const int tx   = tid & 15;       // n = n0 + 4*tx (+64)
    const int ty   = tid >> 4;       // m = m0 + 8*ty + i
    const int lrow = tid >> 2;       // load row 0..63
    const int lkq  = (tid & 3) * 4;  // k quad

    const float* Ag = A + (size_t)(m0 + lrow) * K + lkq;
    const float* Wg = W + (size_t)(n0 + lrow) * K + lkq;

    ull acc[8][4];
#pragma unroll
    for (int i = 0; i < 8; ++i)
#pragma unroll
        for (int j = 0; j < 4; ++j) acc[i][j] = 0ull;

    auto stage = [&](const float4& a0, const float4& a1,
                     const float4& w0, const float4& w1) {
        const float av0[4] = {a0.x, a0.y, a0.z, a0.w};
        const float av1[4] = {a1.x, a1.y, a1.z, a1.w};
        const float wv0[4] = {w0.x, w0.y, w0.z, w0.w};
        const float wv1[4] = {w1.x, w1.y, w1.z, w1.w};
#pragma unroll
        for (int d = 0; d < 4; ++d) {
            int kr = lkq + d;
            As[kr * AS_PITCH + lrow]      = av0[d];
            As[kr * AS_PITCH + lrow + 64] = av1[d];
            Ws[kr * WS_PITCH + lrow]      = wv0[d];
            Ws[kr * WS_PITCH + lrow + 64] = wv1[d];
        }
    };

    {
        float4 a0 = __ldg((const float4*)Ag);
        float4 a1 = __ldg((const float4*)(Ag + (size_t)64 * K));
        float4 w0 = __ldg((const float4*)Wg);
        float4 w1 = __ldg((const float4*)(Wg + (size_t)64 * K));
        stage(a0, a1, w0, w1);
    }
    __syncthreads();

    const int NT = K / 16;
    for (int t = 0; t < NT; ++t) {
        float4 na0, na1, nw0, nw1;
        if (t + 1 < NT) {
            const float* Ag2 = Ag + (t + 1) * 16;
            const float* Wg2 = Wg + (t + 1) * 16;
            na0 = __ldg((const float4*)Ag2);
            na1 = __ldg((const float4*)(Ag2 + (size_t)64 * K));
            nw0 = __ldg((const float4*)Wg2);
            nw1 = __ldg((const float4*)(Wg2 + (size_t)64 * K));
        }

#pragma unroll
        for (int kk = 0; kk < 16; ++kk) {
            ull ad[8];
            {
                float4 v0 = *(const float4*)&As[kk * AS_PITCH + 8 * ty];
                float4 v1 = *(const float4*)&As[kk * AS_PITCH + 8 * ty + 4];
                ad[0] = dup2(v0.x); ad[1] = dup2(v0.y); ad[2] = dup2(v0.z); ad[3] = dup2(v0.w);
                ad[4] = dup2(v1.x); ad[5] = dup2(v1.y); ad[6] = dup2(v1.z); ad[7] = dup2(v1.w);
            }
            ull wp_[4];
            {
                float4 v0 = *(const float4*)&Ws[kk * WS_PITCH + 4 * tx];
                float4 v1 = *(const float4*)&Ws[kk * WS_PITCH + 64 + 4 * tx];
                split4(v0, wp_[0], wp_[1]);
                split4(v1, wp_[2], wp_[3]);
            }
#pragma unroll
            for (int i = 0; i < 8; ++i)
#pragma unroll
                for (int j = 0; j < 4; ++j)
                    acc[i][j] = ffma2(ad[i], wp_[j], acc[i][j]);
        }
        __syncthreads();
        if (t + 1 < NT) {
            stage(na0, na1, nw0, nw1);
            __syncthreads();
        }
    }

    const int nA = n0 + 4 * tx;
    const int nB = n0 + 64 + 4 * tx;
    ull bA0, bA1, bB0, bB1;
    {
        float4 biA = __ldg((const float4*)&bih[nA]);
        float4 bhA = __ldg((const float4*)&bhh[nA]);
        float4 biB = __ldg((const float4*)&bih[nB]);
        float4 bhB = __ldg((const float4*)&bhh[nB]);
        float4 sA = make_float4(biA.x + bhA.x, biA.y + bhA.y, biA.z + bhA.z, biA.w + bhA.w);
        float4 sB = make_float4(biB.x + bhB.x, biB.y + bhB.y, biB.z + bhB.z, biB.w + bhB.w);
        split4(sA, bA0, bA1);
        split4(sB, bB0, bB1);
    }
#pragma unroll
    for (int i = 0; i < 8; ++i) {
        size_t m = (size_t)m0 + 8 * ty + i;
        union { ull u[2]; float4 f; } oA, oB;
        oA.u[0] = fadd2(acc[i][0], bA0);
        oA.u[1] = fadd2(acc[i][1], bA1);
        oB.u[0] = fadd2(acc[i][2], bB0);
        oB.u[1] = fadd2(acc[i][3], bB1);
        *(float4*)&g_xg[m * G4 + nA] = oA.f;
        *(float4*)&g_xg[m * G4 + nB] = oB.f;
    }
}

// ---------------- phase B: persistent recurrent scan ------------------------
// 128 blocks x 256 thr = 16 groups x 8 blocks. Group = 4 batches; block = 32-u.
// Handshake: per-block monotonic flags (st.release.gpu), polled by warp 4
// concurrently with stage-2 gating. FINAL_ONLY additionally starts at the
// group's tail (min over its batches' last-reset+1) — state before is exactly 0.
template<int FINAL_ONLY>
__global__ void __launch_bounds__(256, 1) recur_kernel(const float* __restrict__ Whh,
                                                       const float* __restrict__ mask)
{
    __shared__ __align__(16) float h_sh[CB][H_];   // 4 KB
    __shared__ float part[8][CB][128];             // 16 KB

    const int blk = blockIdx.x;
    const int grp = blk >> 3;          // 0..15
    const int ib  = blk & 7;           // 0..7
    const int B0  = grp * CB;
    const int u0  = ib * 32;
    const int tid = threadIdx.x;
    const int ksub = tid >> 5;         // 0..7
    const int tsub = tid & 31;         // u within tile

    // weights: 4 gate rows x 32 k (16 ull each), resident for the whole scan
    ull w2[4][16];
#pragma unroll
    for (int g = 0; g < 4; ++g) {
        const ulonglong2* wp =
            (const ulonglong2*)(Whh + (size_t)(g * 256 + u0 + tsub) * H_ + ksub * 32);
#pragma unroll
        for (int i = 0; i < 8; ++i) {
            ulonglong2 v = __ldg(wp + i);
            w2[g][2 * i]     = v.x;
            w2[g][2 * i + 1] = v.y;
        }
    }

    for (int i = tid; i < CB * H_; i += 256) ((float*)h_sh)[i] = 0.0f;

    // tail start (FINAL_ONLY): group runs from min tail; slots idle until theirs
    int gstart = 0;
    int my_start = 0;
    if (FINAL_ONLY) {
        int t0 = g_tstart[B0 + 0];
        int t1 = g_tstart[B0 + 1];
        int t2 = g_tstart[B0 + 2];
        int t3 = g_tstart[B0 + 3];
        gstart = min(min(t0, t1), min(t2, t3));
        if (gstart > T_ - 1) gstart = T_ - 1;   // always run >= 1 step (writes hfinal)
    }

    // stage-2 identity (threads < 128: one (b,u) cell)
    const int b2 = (tid >> 5) & 3;
    const int u2 = tid & 31;
    if (FINAL_ONLY && tid < 128) my_start = g_tstart[B0 + b2];
    float c_state = 0.0f;
    const float* xgbase = g_xg + (size_t)(B0 + b2) * T_ * G4 + u0 + u2;
    const float* maskp  = mask + (size_t)(B0 + b2) * T_;
    float x0, x1, x2, x3, mval;
    if (tid < 128) {
        const float* xp = xgbase + (size_t)gstart * G4;
        x0 = __ldg(xp);
        x1 = __ldg(xp + 256);
        x2 = __ldg(xp + 512);
        x3 = __ldg(xp + 768);
        mval = __ldg(maskp + gstart);
    }

    unsigned* flags = &g_flag[grp][0];
    const int lane = tid & 31;
    __syncthreads();

    for (int step = gstart; step < T_; ++step) {
        // ---- GEMM partial: broadcast LDS.128 h reads feed 4 gate rows ----
        ull acc[4][CB];
#pragma unroll
        for (int g = 0; g < 4; ++g)
#pragma unroll
            for (int b = 0; b < CB; ++b) acc[g][b] = 0ull;
#pragma unroll
        for (int b = 0; b < CB; ++b) {
            const ulonglong2* hp = (const ulonglong2*)&h_sh[b][ksub * 32];
#pragma unroll
            for (int kk = 0; kk < 8; ++kk) {
                ulonglong2 hv = hp[kk];
#pragma unroll
                for (int g = 0; g < 4; ++g) {
                    acc[g][b] = ffma2(w2[g][2 * kk],     hv.x, acc[g][b]);
                    acc[g][b] = ffma2(w2[g][2 * kk + 1], hv.y, acc[g][b]);
                }
            }
        }
#pragma unroll
        for (int g = 0; g < 4; ++g)
#pragma unroll
            for (int b = 0; b < CB; ++b)
                part[ksub][b][g * 32 + tsub] = hsum2(acc[g][b]);
        __syncthreads();   // (#1) part ready

        if (tid < 128) {
            // ---- stage-2: gates + state update + publish ----
            float h;
            if (!FINAL_ONLY || step >= my_start) {
                float s0 = x0, s1 = x1, s2 = x2, s3 = x3;
#pragma unroll
                for (int ks = 0; ks < 8; ++ks) {
                    s0 += part[ks][b2][ 0 + u2];
                    s1 += part[ks][b2][32 + u2];
                    s2 += part[ks][b2][64 + u2];
                    s3 += part[ks][b2][96 + u2];
                }
                float c = fsigm(s1) * c_state + fsigm(s0) * ftanh(s2);
                h = fsigm(s3) * ftanh(c);
                h *= mval; c *= mval;
                c_state = c;
            } else {
                c_state = 0.0f;
                h = 0.0f;
            }

            g_hx[step & 1][grp][b2 * H_ + u0 + u2] = h;

            // order the 128 h-stores, then leader releases this block's tag
            asm volatile("bar.sync 1, 128;" ::: "memory");
            if (tid == 0) st_release_gpu(&flags[ib], (unsigned)(step + 1));

            // off-critical-path: hseq/final store + next-step input prefetch
            if (!FINAL_ONLY) {
                g_hseq[((size_t)(B0 + b2) * T_ + step) * H_ + u0 + u2] = h;
            } else if (step == T_ - 1) {
                g_hfinal[(B0 + b2) * H_ + u0 + u2] = h;
            }
            int sn = (step + 1 < T_) ? step + 1 : step;
            const float* xp = xgbase + (size_t)sn * G4;
            x0 = __ldg(xp);
            x1 = __ldg(xp + 256);
            x2 = __ldg(xp + 512);
            x3 = __ldg(xp + 768);
            mval = __ldg(maskp + sn);
        } else if (tid < 160) {
            // ---- warp 4: poll all 8 peer flags, overlapped with stage-2 ----
            const unsigned target = (unsigned)(step + 1);
            bool done = (lane >= GBLK);
            while (true) {
                if (!done) done = (ld_relaxed_gpu(&flags[lane]) >= target);
                if (__ballot_sync(0xffffffffu, done) == 0xffffffffu) break;
            }
            if (lane < GBLK) (void)ld_acquire_gpu(&flags[lane]);  // pair acquire per producer
        }
        __syncthreads();   // (#2) stage-2 done + all flags acquired

        // ---- reload group h(t) into smem (1 float4 per thread) ----
        ((float4*)h_sh)[tid] = __ldcg((const float4*)&g_hx[step & 1][grp][0] + tid);
        __syncthreads();   // (#3) h_sh ready
    }
}

// ---------------- LN + ReLU over layer-0 output (in place) ------------------
__global__ void ln_relu_kernel(const float* __restrict__ g, const float* __restrict__ b)
{
    int row  = blockIdx.x * 8 + (threadIdx.x >> 5);
    int lane = threadIdx.x & 31;
    float* p = g_hseq + (size_t)row * H_;
    float4 v0 = *(float4*)(p + lane * 4);
    float4 v1 = *(float4*)(p + 128 + lane * 4);
    float s = v0.x + v0.y + v0.z + v0.w + v1.x + v1.y + v1.z + v1.w;
    float q = v0.x*v0.x + v0.y*v0.y + v0.z*v0.z + v0.w*v0.w
            + v1.x*v1.x + v1.y*v1.y + v1.z*v1.z + v1.w*v1.w;
#pragma unroll
    for (int o = 16; o; o >>= 1) {
        s += __shfl_xor_sync(0xffffffffu, s, o);
        q += __shfl_xor_sync(0xffffffffu, q, o);
    }
    float mu  = s * (1.0f / 256.0f);
    float var = q * (1.0f / 256.0f) - mu * mu;
    float rs  = rsqrtf(var + 1e-5f);
    int u = lane * 4;
    float4 G0 = *(const float4*)(g + u);       float4 Bb0 = *(const float4*)(b + u);
    float4 G1 = *(const float4*)(g + 128 + u); float4 Bb1 = *(const float4*)(b + 128 + u);
    v0.x = fmaxf(0.0f, (v0.x - mu) * rs * G0.x + Bb0.x);
    v0.y = fmaxf(0.0f, (v0.y - mu) * rs * G0.y + Bb0.y);
    v0.z = fmaxf(0.0f, (v0.z - mu) * rs * G0.z + Bb0.z);
    v0.w = fmaxf(0.0f, (v0.w - mu) * rs * G0.w + Bb0.w);
    v1.x = fmaxf(0.0f, (v1.x - mu) * rs * G1.x + Bb1.x);
    v1.y = fmaxf(0.0f, (v1.y - mu) * rs * G1.y + Bb1.y);
    v1.z = fmaxf(0.0f, (v1.z - mu) * rs * G1.z + Bb1.z);
    v1.w = fmaxf(0.0f, (v1.w - mu) * rs * G1.w + Bb1.w);
    *(float4*)(p + lane * 4)       = v0;
    *(float4*)(p + 128 + lane * 4) = v1;
}

// ---------------- final: LN + ReLU + FC on last-step h of layer 1 -----------
__global__ void final_kernel(const float* __restrict__ lng, const float* __restrict__ lnb,
                             const float* __restrict__ fcW, const float* __restrict__ fcb,
                             float* __restrict__ out)
{
    int b = blockIdx.x;
    int t = threadIdx.x;
    __shared__ float ssum[8], sq[8];
    __shared__ float y[256];
    __shared__ float stats[2];
    float v = g_hfinal[b * H_ + t];
    float s = v, q = v * v;
#pragma unroll
    for (int o = 16; o; o >>= 1) {
        s += __shfl_xor_sync(0xffffffffu, s, o);
        q += __shfl_xor_sync(0xffffffffu, q, o);
    }
    if ((t & 31) == 0) { ssum[t >> 5] = s; sq[t >> 5] = q; }
    __syncthreads();
    if (t == 0) {
        float S = 0.0f, Q = 0.0f;
        for (int i = 0; i < 8; ++i) { S += ssum[i]; Q += sq[i]; }
        float mu  = S * (1.0f / 256.0f);
        float var = Q * (1.0f / 256.0f) - mu * mu;
        stats[0] = mu;
        stats[1] = rsqrtf(var + 1e-5f);
    }
    __syncthreads();
    y[t] = fmaxf(0.0f, (v - stats[0]) * stats[1] * lng[t] + lnb[t]);
    __syncthreads();
    if (t < C_) {
        float a = fcb[t];
        const float* wr = fcW + (size_t)t * H_;
#pragma unroll 8
        for (int u = 0; u < H_; ++u) a = fmaf(y[u], wr[u], a);
        out[b * C_ + t] = a;
    }
}

// ---------------- host entry -------------------------------------------------
extern "C" void kernel_launch(void* const* d_in, const int* in_sizes, int n_in,
                              void* d_out, int out_size)
{
    const float* seq  = (const float*)d_in[0];
    const float* mask = (const float*)d_in[1];
    const float* Wih0 = (const float*)d_in[2];
    const float* Whh0 = (const float*)d_in[3];
    const float* bih0 = (const float*)d_in[4];
    const float* bhh0 = (const float*)d_in[5];
    const float* lng0 = (const float*)d_in[6];
    const float* lnb0 = (const float*)d_in[7];
    const float* Wih1 = (const float*)d_in[8];
    const float* Whh1 = (const float*)d_in[9];
    const float* bih1 = (const float*)d_in[10];
    const float* bhh1 = (const float*)d_in[11];
    const float* lng1 = (const float*)d_in[12];
    const float* lnb1 = (const float*)d_in[13];
    const float* fcW  = (const float*)d_in[14];
    const float* fcb  = (const float*)d_in[15];
    float* out = (float*)d_out;

    const int M = B_ * T_;               // 131072
    dim3 gemm_grid(G4 / 128, M / 128);   // (8, 1024)

    // tail starts (needed by layer-1 GEMM skip + layer-1 recurrence)
    tail_kernel<<<B_, 32>>>(mask);

    // ---- layer 0 (full sequence) ----
    sgemm_xg<I_, 0, 0><<<gemm_grid, 256>>>(seq, Wih0, bih0, bhh0);
    init_bar<<<1, 512>>>();
    recur_kernel<0><<<NGRP * GBLK, 256>>>(Whh0, mask);
    ln_relu_kernel<<<M / 8, 256>>>(lng0, lnb0);

    // ---- layer 1 (tail only: h(T-1) depends only on last reset segment) ----
    sgemm_xg<H_, 1, 1><<<gemm_grid, 256>>>(nullptr, Wih1, bih1, bhh1);
    init_bar<<<1, 512>>>();
    recur_kernel<1><<<NGRP * GBLK, 256>>>(Whh1, mask);

    // ---- head ----
    final_kernel<<<B_, 256>>>(lng1, lnb1, fcW, fcb, out);
}

// round 11
// speedup vs baseline: 13.0083x; 7.0135x over previous
#include <cuda_runtime.h>
#include <math.h>
#include <stddef.h>
#include <stdint.h>

// Problem dims
#define B_  64
#define T_  2048
#define I_  128
#define H_  256
#define G4  1024      // 4*H
#define C_  64

// recurrence: 16 groups x 8 blocks; group owns 4 batches; block owns 32-u tile
#define NGRP 16
#define GBLK 8
#define CB   4

typedef unsigned long long ull;

// ---------------- scratch (static device allocations; no cudaMalloc) --------
__device__ float    g_xg   [(size_t)B_ * T_ * G4];   // 512 MB gate preacts
__device__ float    g_hseq [(size_t)B_ * T_ * H_];   // 128 MB layer-0 h sequence / y0
__device__ float    g_hx   [2][NGRP][CB * H_];       // double-buffered group h slabs
__device__ float    g_hfinal[B_ * H_];               // layer-1 final h
__device__ unsigned g_flag [NGRP][32];               // per-block step tags (128B/group)
__device__ int      g_tstart[B_];                    // per-batch tail start (last reset + 1)

// ---------------- helpers ---------------------------------------------------
__device__ __forceinline__ ull ffma2(ull a, ull b, ull c) {
    ull d;
    asm("fma.rn.f32x2 %0, %1, %2, %3;" : "=l"(d) : "l"(a), "l"(b), "l"(c));
    return d;
}
__device__ __forceinline__ ull fadd2(ull a, ull b) {
    ull d;
    asm("add.rn.f32x2 %0, %1, %2;" : "=l"(d) : "l"(a), "l"(b));
    return d;
}
__device__ __forceinline__ float hsum2(ull v) {
    union { ull u; float2 f; } cv; cv.u = v;
    return cv.f.x + cv.f.y;
}
__device__ __forceinline__ void split4(const float4& v, ull& lo, ull& hi) {
    union { float4 f; ull u[2]; } cv; cv.f = v;
    lo = cv.u[0]; hi = cv.u[1];
}
__device__ __forceinline__ ull dup2(float f) {
    ull d; unsigned u = __float_as_uint(f);
    asm("mov.b64 %0, {%1, %1};" : "=l"(d) : "r"(u));
    return d;
}
__device__ __forceinline__ float fsigm(float x) { return 1.0f / (1.0f + __expf(-x)); }
__device__ __forceinline__ float ftanh(float x) { return 2.0f / (1.0f + __expf(-2.0f * x)) - 1.0f; }

// release/acquire flag ops (gpu scope, bypass L1)
__device__ __forceinline__ void st_release_gpu(unsigned* p, unsigned v) {
    asm volatile("st.release.gpu.u32 [%0], %1;" :: "l"(p), "r"(v) : "memory");
}
__device__ __forceinline__ unsigned ld_relaxed_gpu(const unsigned* p) {
    unsigned v;
    asm volatile("ld.relaxed.gpu.u32 %0, [%1];" : "=r"(v) : "l"(p) : "memory");
    return v;
}
__device__ __forceinline__ unsigned ld_acquire_gpu(const unsigned* p) {
    unsigned v;
    asm volatile("ld.acquire.gpu.u32 %0, [%1];" : "=r"(v) : "l"(p) : "memory");
    return v;
}

// ---------------- init: zero flags -------------------------------------------
__global__ void init_bar() {
    int i = blockIdx.x * blockDim.x + threadIdx.x;
    if (i < NGRP * 32) ((unsigned*)g_flag)[i] = 0u;
}

// ---------------- tail scan: last reset position per batch -------------------
__global__ void tail_kernel(const float* __restrict__ mask) {
    int b = blockIdx.x;
    int lane = threadIdx.x;
    int best = -1;
    for (int t = lane; t < T_; t += 32) {
        if (mask[(size_t)b * T_ + t] == 0.0f && t > best) best = t;
    }
#pragma unroll
    for (int o = 16; o; o >>= 1) {
        int v = __shfl_xor_sync(0xffffffffu, best, o);
        if (v > best) best = v;
    }
    if (lane == 0) g_tstart[b] = best + 1;
}

// ---------------- phase A: xg = A @ W^T + (bih + bhh) -----------------------
// BM=128, BN=128, BK=16, 256 threads, 8m x 8n tile, n-packed FFMA2 accums.
// As [k][m] scalar (read broadcast + register dup); Ws [k][n] transposed.
// Tiles entirely below the batch's tail start exit early (output unused).
#define AS_PITCH 132
#define WS_PITCH 132

template<int K, int USE_HSEQ>
__global__ void __launch_bounds__(256, 2) sgemm_xg(const float* __restrict__ Ain,
                                                   const float* __restrict__ W,
                                                   const float* __restrict__ bih,
                                                   const float* __restrict__ bhh)
{
    const float* A = USE_HSEQ ? (const float*)g_hseq : Ain;
    const int n0 = blockIdx.x * 128;
    const int m0 = blockIdx.y * 128;

    {
        int batch = m0 >> 11;               // 2048 rows per batch, tiles don't cross
        int tile_end = (m0 & 2047) + 127;
        if (tile_end < g_tstart[batch]) return;
    }

    __shared__ __align__(16) float As[16 * AS_PITCH];
    __shared__ __align__(16) float Ws[16 * WS_PITCH];

    const int tid  = threadIdx.x;
    const int tx   = tid & 15;       // n = n0 + 4*tx (+64)
    const int ty   = tid >> 4;       // m = m0 + 8*ty + i
    const int lrow = tid >> 2;       // load row 0..63
    const int lkq  = (tid & 3) * 4;  // k quad

    const float* Ag = A + (size_t)(m0 + lrow) * K + lkq;
    const float* Wg = W + (size_t)(n0 + lrow) * K + lkq;

    ull acc[8][4];
#pragma unroll
    for (int i = 0; i < 8; ++i)
#pragma unroll
        for (int j = 0; j < 4; ++j) acc[i][j] = 0ull;

    auto stage = [&](const float4& a0, const float4& a1,
                     const float4& w0, const float4& w1) {
        const float av0[4] = {a0.x, a0.y, a0.z, a0.w};
        const float av1[4] = {a1.x, a1.y, a1.z, a1.w};
        const float wv0[4] = {w0.x, w0.y, w0.z, w0.w};
        const float wv1[4] = {w1.x, w1.y, w1.z, w1.w};
#pragma unroll
        for (int d = 0; d < 4; ++d) {
            int kr = lkq + d;
            As[kr * AS_PITCH + lrow]      = av0[d];
            As[kr * AS_PITCH + lrow + 64] = av1[d];
            Ws[kr * WS_PITCH + lrow]      = wv0[d];
            Ws[kr * WS_PITCH + lrow + 64] = wv1[d];
        }
    };

    {
        float4 a0 = __ldg((const float4*)Ag);
        float4 a1 = __ldg((const float4*)(Ag + (size_t)64 * K));
        float4 w0 = __ldg((const float4*)Wg);
        float4 w1 = __ldg((const float4*)(Wg + (size_t)64 * K));
        stage(a0, a1, w0, w1);
    }
    __syncthreads();

    const int NT = K / 16;
    for (int t = 0; t < NT; ++t) {
        float4 na0, na1, nw0, nw1;
        if (t + 1 < NT) {
            const float* Ag2 = Ag + (t + 1) * 16;
            const float* Wg2 = Wg + (t + 1) * 16;
            na0 = __ldg((const float4*)Ag2);
            na1 = __ldg((const float4*)(Ag2 + (size_t)64 * K));
            nw0 = __ldg((const float4*)Wg2);
            nw1 = __ldg((const float4*)(Wg2 + (size_t)64 * K));
        }

#pragma unroll
        for (int kk = 0; kk < 16; ++kk) {
            ull ad[8];
            {
                float4 v0 = *(const float4*)&As[kk * AS_PITCH + 8 * ty];
                float4 v1 = *(const float4*)&As[kk * AS_PITCH + 8 * ty + 4];
                ad[0] = dup2(v0.x); ad[1] = dup2(v0.y); ad[2] = dup2(v0.z); ad[3] = dup2(v0.w);
                ad[4] = dup2(v1.x); ad[5] = dup2(v1.y); ad[6] = dup2(v1.z); ad[7] = dup2(v1.w);
            }
            ull wp_[4];
            {
                float4 v0 = *(const float4*)&Ws[kk * WS_PITCH + 4 * tx];
                float4 v1 = *(const float4*)&Ws[kk * WS_PITCH + 64 + 4 * tx];
                split4(v0, wp_[0], wp_[1]);
                split4(v1, wp_[2], wp_[3]);
            }
#pragma unroll
            for (int i = 0; i < 8; ++i)
#pragma unroll
                for (int j = 0; j < 4; ++j)
                    acc[i][j] = ffma2(ad[i], wp_[j], acc[i][j]);
        }
        __syncthreads();
        if (t + 1 < NT) {
            stage(na0, na1, nw0, nw1);
            __syncthreads();
        }
    }

    const int nA = n0 + 4 * tx;
    const int nB = n0 + 64 + 4 * tx;
    ull bA0, bA1, bB0, bB1;
    {
        float4 biA = __ldg((const float4*)&bih[nA]);
        float4 bhA = __ldg((const float4*)&bhh[nA]);
        float4 biB = __ldg((const float4*)&bih[nB]);
        float4 bhB = __ldg((const float4*)&bhh[nB]);
        float4 sA = make_float4(biA.x + bhA.x, biA.y + bhA.y, biA.z + bhA.z, biA.w + bhA.w);
        float4 sB = make_float4(biB.x + bhB.x, biB.y + bhB.y, biB.z + bhB.z, biB.w + bhB.w);
        split4(sA, bA0, bA1);
        split4(sB, bB0, bB1);
    }
#pragma unroll
    for (int i = 0; i < 8; ++i) {
        size_t m = (size_t)m0 + 8 * ty + i;
        union { ull u[2]; float4 f; } oA, oB;
        oA.u[0] = fadd2(acc[i][0], bA0);
        oA.u[1] = fadd2(acc[i][1], bA1);
        oB.u[0] = fadd2(acc[i][2], bB0);
        oB.u[1] = fadd2(acc[i][3], bB1);
        *(float4*)&g_xg[m * G4 + nA] = oA.f;
        *(float4*)&g_xg[m * G4 + nB] = oB.f;
    }
}

// ---------------- phase B: persistent recurrent scan ------------------------
// 128 blocks x 256 thr = 16 groups x 8 blocks. Group = 4 batches; block = 32-u.
// Handshake: per-block monotonic flags (st.release.gpu), polled by warp 4
// concurrently with stage-2 gating. BOTH layers start at the group tail
// (min over its batches' last-reset+1) — the pre-tail state is exactly 0,
// and downstream consumers never read pre-tail rows.
template<int FINAL_ONLY>
__global__ void __launch_bounds__(256, 1) recur_kernel(const float* __restrict__ Whh,
                                                       const float* __restrict__ mask)
{
    __shared__ __align__(16) float h_sh[CB][H_];   // 4 KB
    __shared__ float part[8][CB][128];             // 16 KB

    const int blk = blockIdx.x;
    const int grp = blk >> 3;          // 0..15
    const int ib  = blk & 7;           // 0..7
    const int B0  = grp * CB;
    const int u0  = ib * 32;
    const int tid = threadIdx.x;
    const int ksub = tid >> 5;         // 0..7
    const int tsub = tid & 31;         // u within tile

    // weights: 4 gate rows x 32 k (16 ull each), resident for the whole scan
    ull w2[4][16];
#pragma unroll
    for (int g = 0; g < 4; ++g) {
        const ulonglong2* wp =
            (const ulonglong2*)(Whh + (size_t)(g * 256 + u0 + tsub) * H_ + ksub * 32);
#pragma unroll
        for (int i = 0; i < 8; ++i) {
            ulonglong2 v = __ldg(wp + i);
            w2[g][2 * i]     = v.x;
            w2[g][2 * i + 1] = v.y;
        }
    }

    for (int i = tid; i < CB * H_; i += 256) ((float*)h_sh)[i] = 0.0f;

    // tail start: group runs from min tail; slots idle (output 0) until theirs
    int gstart, my_start = 0;
    {
        int t0 = g_tstart[B0 + 0];
        int t1 = g_tstart[B0 + 1];
        int t2 = g_tstart[B0 + 2];
        int t3 = g_tstart[B0 + 3];
        gstart = min(min(t0, t1), min(t2, t3));
        if (gstart > T_ - 1) gstart = T_ - 1;   // always run >= 1 step
    }

    // stage-2 identity (threads < 128: one (b,u) cell)
    const int b2 = (tid >> 5) & 3;
    const int u2 = tid & 31;
    if (tid < 128) my_start = g_tstart[B0 + b2];
    float c_state = 0.0f;
    const float* xgbase = g_xg + (size_t)(B0 + b2) * T_ * G4 + u0 + u2;
    const float* maskp  = mask + (size_t)(B0 + b2) * T_;
    float x0, x1, x2, x3, mval;
    if (tid < 128) {
        const float* xp = xgbase + (size_t)gstart * G4;
        x0 = __ldg(xp);
        x1 = __ldg(xp + 256);
        x2 = __ldg(xp + 512);
        x3 = __ldg(xp + 768);
        mval = __ldg(maskp + gstart);
    }

    unsigned* flags = &g_flag[grp][0];
    const int lane = tid & 31;
    __syncthreads();

    for (int step = gstart; step < T_; ++step) {
        // ---- GEMM partial: broadcast LDS.128 h reads feed 4 gate rows ----
        ull acc[4][CB];
#pragma unroll
        for (int g = 0; g < 4; ++g)
#pragma unroll
            for (int b = 0; b < CB; ++b) acc[g][b] = 0ull;
#pragma unroll
        for (int b = 0; b < CB; ++b) {
            const ulonglong2* hp = (const ulonglong2*)&h_sh[b][ksub * 32];
#pragma unroll
            for (int kk = 0; kk < 8; ++kk) {
                ulonglong2 hv = hp[kk];
#pragma unroll
                for (int g = 0; g < 4; ++g) {
                    acc[g][b] = ffma2(w2[g][2 * kk],     hv.x, acc[g][b]);
                    acc[g][b] = ffma2(w2[g][2 * kk + 1], hv.y, acc[g][b]);
                }
            }
        }
#pragma unroll
        for (int g = 0; g < 4; ++g)
#pragma unroll
            for (int b = 0; b < CB; ++b)
                part[ksub][b][g * 32 + tsub] = hsum2(acc[g][b]);
        __syncthreads();   // (#1) part ready

        if (tid < 128) {
            // ---- stage-2: gates + state update + publish ----
            float h;
            if (step >= my_start) {
                float s0 = x0, s1 = x1, s2 = x2, s3 = x3;
#pragma unroll
                for (int ks = 0; ks < 8; ++ks) {
                    s0 += part[ks][b2][ 0 + u2];
                    s1 += part[ks][b2][32 + u2];
                    s2 += part[ks][b2][64 + u2];
                    s3 += part[ks][b2][96 + u2];
                }
                float c = fsigm(s1) * c_state + fsigm(s0) * ftanh(s2);
                h = fsigm(s3) * ftanh(c);
                h *= mval; c *= mval;
                c_state = c;
            } else {
                c_state = 0.0f;
                h = 0.0f;
            }

            g_hx[step & 1][grp][b2 * H_ + u0 + u2] = h;

            // order the 128 h-stores, then leader releases this block's tag
            asm volatile("bar.sync 1, 128;" ::: "memory");
            if (tid == 0) st_release_gpu(&flags[ib], (unsigned)(step + 1));

            // off-critical-path: hseq/final store + next-step input prefetch
            if (!FINAL_ONLY) {
                g_hseq[((size_t)(B0 + b2) * T_ + step) * H_ + u0 + u2] = h;
            } else if (step == T_ - 1) {
                g_hfinal[(B0 + b2) * H_ + u0 + u2] = h;
            }
            int sn = (step + 1 < T_) ? step + 1 : step;
            const float* xp = xgbase + (size_t)sn * G4;
            x0 = __ldg(xp);
            x1 = __ldg(xp + 256);
            x2 = __ldg(xp + 512);
            x3 = __ldg(xp + 768);
            mval = __ldg(maskp + sn);
        } else if (tid < 160) {
            // ---- warp 4: poll all 8 peer flags, overlapped with stage-2 ----
            const unsigned target = (unsigned)(step + 1);
            bool done = (lane >= GBLK);
            while (true) {
                if (!done) done = (ld_relaxed_gpu(&flags[lane]) >= target);
                if (__ballot_sync(0xffffffffu, done) == 0xffffffffu) break;
            }
            if (lane < GBLK) (void)ld_acquire_gpu(&flags[lane]);  // pair acquire per producer
        }
        __syncthreads();   // (#2) stage-2 done + all flags acquired

        // ---- reload group h(t) into smem (1 float4 per thread) ----
        ((float4*)h_sh)[tid] = __ldcg((const float4*)&g_hx[step & 1][grp][0] + tid);
        __syncthreads();   // (#3) h_sh ready
    }
}

// ---------------- LN + ReLU over layer-0 output (in place, tail rows only) --
__global__ void ln_relu_kernel(const float* __restrict__ g, const float* __restrict__ b)
{
    int row  = blockIdx.x * 8 + (threadIdx.x >> 5);
    int lane = threadIdx.x & 31;
    if ((row & 2047) < g_tstart[row >> 11]) return;   // pre-tail rows unused
    float* p = g_hseq + (size_t)row * H_;
    float4 v0 = *(float4*)(p + lane * 4);
    float4 v1 = *(float4*)(p + 128 + lane * 4);
    float s = v0.x + v0.y + v0.z + v0.w + v1.x + v1.y + v1.z + v1.w;
    float q = v0.x*v0.x + v0.y*v0.y + v0.z*v0.z + v0.w*v0.w
            + v1.x*v1.x + v1.y*v1.y + v1.z*v1.z + v1.w*v1.w;
#pragma unroll
    for (int o = 16; o; o >>= 1) {
        s += __shfl_xor_sync(0xffffffffu, s, o);
        q += __shfl_xor_sync(0xffffffffu, q, o);
    }
    float mu  = s * (1.0f / 256.0f);
    float var = q * (1.0f / 256.0f) - mu * mu;
    float rs  = rsqrtf(var + 1e-5f);
    int u = lane * 4;
    float4 G0 = *(const float4*)(g + u);       float4 Bb0 = *(const float4*)(b + u);
    float4 G1 = *(const float4*)(g + 128 + u); float4 Bb1 = *(const float4*)(b + 128 + u);
    v0.x = fmaxf(0.0f, (v0.x - mu) * rs * G0.x + Bb0.x);
    v0.y = fmaxf(0.0f, (v0.y - mu) * rs * G0.y + Bb0.y);
    v0.z = fmaxf(0.0f, (v0.z - mu) * rs * G0.z + Bb0.z);
    v0.w = fmaxf(0.0f, (v0.w - mu) * rs * G0.w + Bb0.w);
    v1.x = fmaxf(0.0f, (v1.x - mu) * rs * G1.x + Bb1.x);
    v1.y = fmaxf(0.0f, (v1.y - mu) * rs * G1.y + Bb1.y);
    v1.z = fmaxf(0.0f, (v1.z - mu) * rs * G1.z + Bb1.z);
    v1.w = fmaxf(0.0f, (v1.w - mu) * rs * G1.w + Bb1.w);
    *(float4*)(p + lane * 4)       = v0;
    *(float4*)(p + 128 + lane * 4) = v1;
}

// ---------------- final: LN + ReLU + FC on last-step h of layer 1 -----------
__global__ void final_kernel(const float* __restrict__ lng, const float* __restrict__ lnb,
                             const float* __restrict__ fcW, const float* __restrict__ fcb,
                             float* __restrict__ out)
{
    int b = blockIdx.x;
    int t = threadIdx.x;
    __shared__ float ssum[8], sq[8];
    __shared__ float y[256];
    __shared__ float stats[2];
    float v = g_hfinal[b * H_ + t];
    float s = v, q = v * v;
#pragma unroll
    for (int o = 16; o; o >>= 1) {
        s += __shfl_xor_sync(0xffffffffu, s, o);
        q += __shfl_xor_sync(0xffffffffu, q, o);
    }
    if ((t & 31) == 0) { ssum[t >> 5] = s; sq[t >> 5] = q; }
    __syncthreads();
    if (t == 0) {
        float S = 0.0f, Q = 0.0f;
        for (int i = 0; i < 8; ++i) { S += ssum[i]; Q += sq[i]; }
        float mu  = S * (1.0f / 256.0f);
        float var = Q * (1.0f / 256.0f) - mu * mu;
        stats[0] = mu;
        stats[1] = rsqrtf(var + 1e-5f);
    }
    __syncthreads();
    y[t] = fmaxf(0.0f, (v - stats[0]) * stats[1] * lng[t] + lnb[t]);
    __syncthreads();
    if (t < C_) {
        float a = fcb[t];
        const float* wr = fcW + (size_t)t * H_;
#pragma unroll 8
        for (int u = 0; u < H_; ++u) a = fmaf(y[u], wr[u], a);
        out[b * C_ + t] = a;
    }
}

// ---------------- host entry -------------------------------------------------
extern "C" void kernel_launch(void* const* d_in, const int* in_sizes, int n_in,
                              void* d_out, int out_size)
{
    const float* seq  = (const float*)d_in[0];
    const float* mask = (const float*)d_in[1];
    const float* Wih0 = (const float*)d_in[2];
    const float* Whh0 = (const float*)d_in[3];
    const float* bih0 = (const float*)d_in[4];
    const float* bhh0 = (const float*)d_in[5];
    const float* lng0 = (const float*)d_in[6];
    const float* lnb0 = (const float*)d_in[7];
    const float* Wih1 = (const float*)d_in[8];
    const float* Whh1 = (const float*)d_in[9];
    const float* bih1 = (const float*)d_in[10];
    const float* bhh1 = (const float*)d_in[11];
    const float* lng1 = (const float*)d_in[12];
    const float* lnb1 = (const float*)d_in[13];
    const float* fcW  = (const float*)d_in[14];
    const float* fcb  = (const float*)d_in[15];
    float* out = (float*)d_out;

    const int M = B_ * T_;               // 131072
    dim3 gemm_grid(G4 / 128, M / 128);   // (8, 1024)

    // tail starts (consumed by both GEMMs, both recurrences, ln_relu)
    tail_kernel<<<B_, 32>>>(mask);

    // ---- layer 0 (tail only) ----
    sgemm_xg<I_, 0><<<gemm_grid, 256>>>(seq, Wih0, bih0, bhh0);
    init_bar<<<1, 512>>>();
    recur_kernel<0><<<NGRP * GBLK, 256>>>(Whh0, mask);
    ln_relu_kernel<<<M / 8, 256>>>(lng0, lnb0);

    // ---- layer 1 (tail only) ----
    sgemm_xg<H_, 1><<<gemm_grid, 256>>>(nullptr, Wih1, bih1, bhh1);
    init_bar<<<1, 512>>>();
    recur_kernel<1><<<NGRP * GBLK, 256>>>(Whh1, mask);

    // ---- head ----
    final_kernel<<<B_, 256>>>(lng1, lnb1, fcW, fcb, out);
}